// round 15
// baseline (speedup 1.0000x reference)
#include <cuda_runtime.h>
#include <cuda_fp16.h>
#include <cstdint>
#include <cstddef>

#define S_    2048
#define B_    4
#define INDIM 64
#define H_    1024
#define DFF_  1024
#define OUTD  64
#define L_    3
#define NHEAD 4
#define DH    (H_ / NHEAD)   // 256
#define WIN   4
#define TOK   (S_ * B_)      // 8192
#define EPS   1e-5f
#define NPADH 256            // padded head N

// ---------------- scratch (static device globals) -----------------------------
__device__ float g_x[TOK * H_];
__device__ float g_bout_pad[NPADH];

__device__ __align__(256) __half g_qkv2[TOK * 3 * H_];
__device__ __align__(256) __half g_tmp2[TOK * H_];
__device__ __align__(256) __half g_src2[TOK * INDIM];
__device__ __align__(256) __half g_x2[TOK * H_];
__device__ __align__(256) __half g_ctx2[TOK * H_];
__device__ __align__(256) __half g_h12[TOK * H_];
__device__ __align__(256) __half g_wenc2[H_ * INDIM];
__device__ __align__(256) __half g_wqkv2[L_ * 3 * H_ * H_];
__device__ __align__(256) __half g_wo2[L_ * H_ * H_];
__device__ __align__(256) __half g_w12[L_ * DFF_ * H_];
__device__ __align__(256) __half g_w22[L_ * H_ * DFF_];
__device__ __align__(256) __half g_wout2[NPADH * H_];

// ---------------- helpers -----------------------------------------------------
__device__ __forceinline__ uint32_t smem_to_u32(const void* p) {
    uint32_t a;
    asm("{ .reg .u64 t; cvta.to.shared.u64 t, %1; cvt.u32.u64 %0, t; }"
        : "=r"(a) : "l"(p));
    return a;
}
__device__ __forceinline__ uint32_t pack_h2(__half a, __half b) {
    __half2 t = __halves2half2(a, b);
    return *reinterpret_cast<uint32_t*>(&t);
}
__device__ __forceinline__ void cp_async16(uint32_t dst, const void* src) {
    asm volatile("cp.async.cg.shared.global [%0], [%1], 16;"
                 :: "r"(dst), "l"(src) : "memory");
}
__device__ __forceinline__ void cp_commit() {
    asm volatile("cp.async.commit_group;" ::: "memory");
}
__device__ __forceinline__ void cp_wait2() {
    asm volatile("cp.async.wait_group 2;" ::: "memory");
}
__device__ __forceinline__ void ldmx4(uint32_t* r, uint32_t a) {
    asm volatile("ldmatrix.sync.aligned.m8n8.x4.shared.b16 {%0,%1,%2,%3}, [%4];"
                 : "=r"(r[0]), "=r"(r[1]), "=r"(r[2]), "=r"(r[3]) : "r"(a));
}
__device__ __forceinline__ void mma16816(float* d, const uint32_t* a,
                                         uint32_t b0, uint32_t b1) {
    asm volatile("mma.sync.aligned.m16n8k16.row.col.f32.f16.f16.f32 "
                 "{%0,%1,%2,%3}, {%4,%5,%6,%7}, {%8,%9}, {%0,%1,%2,%3};"
                 : "+f"(d[0]), "+f"(d[1]), "+f"(d[2]), "+f"(d[3])
                 : "r"(a[0]), "r"(a[1]), "r"(a[2]), "r"(a[3]), "r"(b0), "r"(b1));
}
__device__ __forceinline__ void load8h(const __half* p, float* f) {
    uint4 u = *(const uint4*)p;
    const uint32_t w[4] = { u.x, u.y, u.z, u.w };
#pragma unroll
    for (int i = 0; i < 4; i++) {
        __half2 h2 = *reinterpret_cast<const __half2*>(&w[i]);
        float2 f2 = __half22float2(h2);
        f[2 * i] = f2.x; f[2 * i + 1] = f2.y;
    }
}

// ---------------- conversion kernels ------------------------------------------
__device__ __forceinline__ void cast_quad(const float* in, uint32_t* o) {
    float4 v = *(const float4*)in;
    o[0] = pack_h2(__float2half(v.x), __float2half(v.y));
    o[1] = pack_h2(__float2half(v.z), __float2half(v.w));
}

__global__ void conv_seg2(const float* __restrict__ a, const float* __restrict__ b,
                          __half* __restrict__ oa, __half* __restrict__ ob, int nqA, int nqTot)
{
    int i = blockIdx.x * blockDim.x + threadIdx.x;
    if (i >= nqTot) return;
    if (i < nqA) cast_quad(a + 4 * (size_t)i, reinterpret_cast<uint32_t*>(oa) + 2 * (size_t)i);
    else {
        int j = i - nqA;
        cast_quad(b + 4 * (size_t)j, reinterpret_cast<uint32_t*>(ob) + 2 * (size_t)j);
    }
}

__global__ void conv_cast(const float* __restrict__ in, __half* __restrict__ out, int nq)
{
    int i = blockIdx.x * blockDim.x + threadIdx.x;
    if (i >= nq) return;
    cast_quad(in + 4 * (size_t)i, reinterpret_cast<uint32_t*>(out) + 2 * (size_t)i);
}

__global__ void conv_cast3(const float* __restrict__ a, const float* __restrict__ b,
                           const float* __restrict__ c,
                           __half* __restrict__ oa, __half* __restrict__ ob,
                           __half* __restrict__ oc, int nq)
{
    int i = blockIdx.x * blockDim.x + threadIdx.x;
    if (i >= nq) return;
    const float* in = (blockIdx.y == 0) ? a : (blockIdx.y == 1) ? b : c;
    __half* out = (blockIdx.y == 0) ? oa : (blockIdx.y == 1) ? ob : oc;
    cast_quad(in + 4 * (size_t)i, reinterpret_cast<uint32_t*>(out) + 2 * (size_t)i);
}

__global__ void conv_wout(const float* __restrict__ W, __half* __restrict__ out,
                          const float* __restrict__ bin, float* __restrict__ bpad, int nq)
{
    int i = blockIdx.x * blockDim.x + threadIdx.x;
    if (i < NPADH) bpad[i] = (i < OUTD) ? bin[i] : 0.f;
    if (i >= nq) return;
    uint32_t* o = reinterpret_cast<uint32_t*>(out) + 2 * (size_t)i;
    size_t e = 4 * (size_t)i;
    if (e < (size_t)OUTD * H_) cast_quad(W + e, o);
    else { o[0] = 0; o[1] = 0; }
}

// ---------------- fp16 HMMA GEMM (256 thr, 128x256 CTA, 64x64 warp) -----------
// C[M,Nout] = A2[M,K] @ B2[N,K]^T + bias.  M%128==0, N%256==0, K%64==0.
// mode bits: 1 = write fp32 C (cols < Nout), 2 = write fp16 C2, 4 = relu
#define NSTG  4
#define STGB  49152                 // A 16KB + B 32KB
#define GSMEM (NSTG * STGB)         // 196608

__global__ __launch_bounds__(256, 1)
void gemm_fp16(const __half* __restrict__ A2, const __half* __restrict__ B2,
               const float* __restrict__ bias, float* __restrict__ C,
               __half* __restrict__ C2,
               int M, int N, int K, int Nout, int mode)
{
    extern __shared__ char smem[];
    const uint32_t sb = smem_to_u32(smem);
    const int tid  = threadIdx.x;
    const int wid  = tid >> 5;
    const int lane = tid & 31;
    const int warp_m = wid >> 2;        // 0..1 -> 64-row block
    const int warp_n = wid & 3;         // 0..3 -> 64-col block
    const int tile_m = blockIdx.y * 128;
    const int tile_n = blockIdx.x * 256;
    const int NC = K >> 6;

    const int ra = tid >> 3;            // 0..31
    const int ca = tid & 7;
    const __half* gA = A2 + (size_t)(tile_m + ra) * K + ca * 8;
    const __half* gB = B2 + (size_t)(tile_n + ra) * K + ca * 8;
    const uint32_t dA = (uint32_t)(ra * 128 + ((ca ^ (ra & 7)) << 4));

    float acc[4][8][4];
#pragma unroll
    for (int i = 0; i < 4; i++)
#pragma unroll
        for (int j = 0; j < 8; j++)
#pragma unroll
            for (int k = 0; k < 4; k++) acc[i][j][k] = 0.f;

    auto issue = [&](int stage, int chunk) {
        uint32_t s = sb + stage * STGB;
        size_t ko = (size_t)chunk * 64;
#pragma unroll
        for (int i = 0; i < 4; i++)
            cp_async16(s + dA + i * 4096, gA + ko + (size_t)(32 * i) * K);
#pragma unroll
        for (int i = 0; i < 8; i++)
            cp_async16(s + 16384 + dA + i * 4096, gB + ko + (size_t)(32 * i) * K);
        cp_commit();
    };

    issue(0, 0);
    if (1 < NC) issue(1, 1); else cp_commit();
    if (2 < NC) issue(2, 2); else cp_commit();

    const int l16 = lane & 15;
    const int g   = lane >> 3;

    // fragment double buffers
    uint32_t afr[2][4][4], bfr[2][4][4];

    auto load_frag = [&](uint32_t sA, uint32_t sB, int ks, int buf) {
#pragma unroll
        for (int mt = 0; mt < 4; mt++) {
            int r = warp_m * 64 + mt * 16 + l16;
            uint32_t ku = (uint32_t)((ks * 2 + (lane >> 4)) ^ (r & 7));
            ldmx4(afr[buf][mt], sA + (uint32_t)r * 128 + (ku << 4));
        }
#pragma unroll
        for (int p = 0; p < 4; p++) {
            int rn = warp_n * 64 + p * 16 + (g >> 1) * 8 + (lane & 7);
            uint32_t ku = (uint32_t)((ks * 2 + (g & 1)) ^ (rn & 7));
            ldmx4(bfr[buf][p], sB + (uint32_t)rn * 128 + (ku << 4));
        }
    };

    for (int c = 0; c < NC; c++) {
        cp_wait2();
        __syncthreads();
        if (c + 3 < NC) issue((c + 3) & 3, c + 3); else cp_commit();

        uint32_t sA = sb + (c & 3) * STGB;
        uint32_t sB = sA + 16384;
        load_frag(sA, sB, 0, 0);
#pragma unroll
        for (int ks = 0; ks < 4; ks++) {
            int cur = ks & 1;
            if (ks < 3) load_frag(sA, sB, ks + 1, 1 - cur);
#pragma unroll
            for (int mt = 0; mt < 4; mt++)
#pragma unroll
                for (int p = 0; p < 4; p++) {
                    mma16816(acc[mt][2 * p],     afr[cur][mt], bfr[cur][p][0], bfr[cur][p][1]);
                    mma16816(acc[mt][2 * p + 1], afr[cur][mt], bfr[cur][p][2], bfr[cur][p][3]);
                }
        }
    }

    // epilogue
    const int r0    = lane >> 2;
    const int cpair = (lane & 3) * 2;
#pragma unroll
    for (int mt = 0; mt < 4; mt++) {
#pragma unroll
        for (int nt = 0; nt < 8; nt++) {
            int n  = tile_n + warp_n * 64 + nt * 8 + cpair;
            int m0 = tile_m + warp_m * 64 + mt * 16 + r0;
            if (n >= Nout) continue;
            float2 bv = *(const float2*)(bias + n);
            float v[2][2];
            v[0][0] = acc[mt][nt][0] + bv.x; v[0][1] = acc[mt][nt][1] + bv.y;
            v[1][0] = acc[mt][nt][2] + bv.x; v[1][1] = acc[mt][nt][3] + bv.y;
            if (mode & 4) {
#pragma unroll
                for (int i = 0; i < 2; i++) {
                    v[i][0] = fmaxf(v[i][0], 0.f); v[i][1] = fmaxf(v[i][1], 0.f);
                }
            }
            if (mode & 1) {
                *(float2*)(C + (size_t)m0 * Nout + n)       = make_float2(v[0][0], v[0][1]);
                *(float2*)(C + (size_t)(m0 + 8) * Nout + n) = make_float2(v[1][0], v[1][1]);
            }
            if (mode & 2) {
#pragma unroll
                for (int i = 0; i < 2; i++) {
                    int m = m0 + i * 8;
                    *(reinterpret_cast<uint32_t*>(C2) + (((size_t)m * Nout + n) >> 1)) =
                        pack_h2(__float2half(v[i][0]), __float2half(v[i][1]));
                }
            }
        }
    }
}

// ---------------- banded attention (fp16 qkv in, fp16 ctx out) -----------------
__global__ __launch_bounds__(256)
void attn_kernel(const __half* __restrict__ qkv, __half* __restrict__ ctx2)
{
    int w    = (blockIdx.x * blockDim.x + threadIdx.x) >> 5;
    int lane = threadIdx.x & 31;
    if (w >= TOK * NHEAD) return;
    int t = w >> 2;
    int h = w & 3;
    int s = t / B_;
    int b = t - s * B_;

    float q[8];
    load8h(qkv + (size_t)t * (3 * H_) + h * DH + lane * 8, q);

    int lo  = s - WIN; if (lo < 0) lo = 0;
    int cnt = s - lo + 1;

    float sc[WIN + 1];
#pragma unroll
    for (int j = 0; j <= WIN; j++) {
        sc[j] = -1e30f;
        if (j < cnt) {
            int tj = (lo + j) * B_ + b;
            float k[8];
            load8h(qkv + (size_t)tj * (3 * H_) + H_ + h * DH + lane * 8, k);
            float p = 0.f;
#pragma unroll
            for (int i = 0; i < 8; i++) p = fmaf(q[i], k[i], p);
#pragma unroll
            for (int o = 16; o; o >>= 1) p += __shfl_xor_sync(0xFFFFFFFFu, p, o);
            sc[j] = p * 0.0625f;
        }
    }
    float m = sc[0];
#pragma unroll
    for (int j = 1; j <= WIN; j++) m = fmaxf(m, sc[j]);
    float e[WIN + 1];
    float se = 0.f;
#pragma unroll
    for (int j = 0; j <= WIN; j++) {
        e[j] = (j < cnt) ? __expf(sc[j] - m) : 0.f;
        se += e[j];
    }
    float inv = 1.f / se;

    float cx[8];
#pragma unroll
    for (int i = 0; i < 8; i++) cx[i] = 0.f;
    for (int j = 0; j < cnt; j++) {
        int tj = (lo + j) * B_ + b;
        float vv[8];
        load8h(qkv + (size_t)tj * (3 * H_) + 2 * H_ + h * DH + lane * 8, vv);
        float a = e[j] * inv;
#pragma unroll
        for (int i = 0; i < 8; i++) cx[i] = fmaf(a, vv[i], cx[i]);
    }

    size_t e0 = (size_t)t * H_ + h * DH + lane * 8;
    uint32_t wbuf[4];
#pragma unroll
    for (int p = 0; p < 4; p++)
        wbuf[p] = pack_h2(__float2half(cx[2 * p]), __float2half(cx[2 * p + 1]));
    *(uint4*)(reinterpret_cast<uint32_t*>(ctx2) + (e0 >> 1)) = *(uint4*)wbuf;
}

// ---------------- residual + LayerNorm (fp16 delta in, fp32+fp16 out) ---------
__device__ __forceinline__ float block_sum(float v, float* red)
{
#pragma unroll
    for (int o = 16; o; o >>= 1) v += __shfl_xor_sync(0xFFFFFFFFu, v, o);
    int wid = threadIdx.x >> 5, lane = threadIdx.x & 31;
    if (lane == 0) red[wid] = v;
    __syncthreads();
    if (threadIdx.x < 32) {
        float r = (threadIdx.x < 8) ? red[threadIdx.x] : 0.f;
#pragma unroll
        for (int o = 4; o; o >>= 1) r += __shfl_xor_sync(0xFFFFFFFFu, r, o);
        if (threadIdx.x == 0) red[0] = r;
    }
    __syncthreads();
    float r = red[0];
    __syncthreads();
    return r;
}

__global__ __launch_bounds__(256)
void resid_ln_kernel(float* __restrict__ x, const __half* __restrict__ delta2,
                     const float* __restrict__ scale, const float* __restrict__ bias,
                     __half* __restrict__ x2)
{
    __shared__ float red[8];
    int t   = blockIdx.x;
    int tid = threadIdx.x;
    size_t base = (size_t)t * H_ + tid * 4;

    float4 v = *(const float4*)(x + base);
    uint2 du = *(const uint2*)(reinterpret_cast<const uint32_t*>(delta2) + (base >> 1));
    __half2 d0 = *reinterpret_cast<const __half2*>(&du.x);
    __half2 d1 = *reinterpret_cast<const __half2*>(&du.y);
    float2 f0 = __half22float2(d0);
    float2 f1 = __half22float2(d1);
    v.x += f0.x; v.y += f0.y; v.z += f1.x; v.w += f1.y;

    float s = v.x + v.y + v.z + v.w;
    float mean = block_sum(s, red) * (1.0f / H_);

    float dx = v.x - mean, dy = v.y - mean, dz = v.z - mean, dw = v.w - mean;
    float sq = dx * dx + dy * dy + dz * dz + dw * dw;
    float var = block_sum(sq, red) * (1.0f / H_);
    float rstd = rsqrtf(var + EPS);

    float4 sc = *(const float4*)(scale + tid * 4);
    float4 bi = *(const float4*)(bias + tid * 4);
    float4 o;
    o.x = dx * rstd * sc.x + bi.x;
    o.y = dy * rstd * sc.y + bi.y;
    o.z = dz * rstd * sc.z + bi.z;
    o.w = dw * rstd * sc.w + bi.w;
    *(float4*)(x + base) = o;

    uint32_t wbuf[2];
    wbuf[0] = pack_h2(__float2half(o.x), __float2half(o.y));
    wbuf[1] = pack_h2(__float2half(o.z), __float2half(o.w));
    *(uint2*)(reinterpret_cast<uint32_t*>(x2) + (base >> 1)) = *(uint2*)wbuf;
}

// ---------------- host orchestration ------------------------------------------
static inline void run_gemm(const __half* A2, const __half* B2,
                            const float* bias, float* C, __half* C2,
                            int M, int N, int K, int Nout, int mode)
{
    static int attr_set = 0;
    if (!attr_set) {
        cudaFuncSetAttribute(gemm_fp16, cudaFuncAttributeMaxDynamicSharedMemorySize, GSMEM);
        attr_set = 1;
    }
    dim3 grid(N / 256, M / 128);
    gemm_fp16<<<grid, 256, GSMEM>>>(A2, B2, bias, C, C2, M, N, K, Nout, mode);
}

extern "C" void kernel_launch(void* const* d_in, const int* in_sizes, int n_in,
                              void* d_out, int out_size)
{
    const float* src   = (const float*)d_in[0];
    const float* Wenc  = (const float*)d_in[1];
    const float* benc  = (const float*)d_in[2];
    const float* Wqkv  = (const float*)d_in[3];
    const float* bqkv  = (const float*)d_in[4];
    const float* Wo    = (const float*)d_in[5];
    const float* bo    = (const float*)d_in[6];
    const float* W1    = (const float*)d_in[7];
    const float* b1    = (const float*)d_in[8];
    const float* W2    = (const float*)d_in[9];
    const float* b2    = (const float*)d_in[10];
    const float* ln1_s = (const float*)d_in[11];
    const float* ln1_b = (const float*)d_in[12];
    const float* ln2_s = (const float*)d_in[13];
    const float* ln2_b = (const float*)d_in[14];
    const float* Wout  = (const float*)d_in[15];
    const float* bout  = (const float*)d_in[16];
    float* out = (float*)d_out;

    float *x, *bout_pad;
    __half *qkv2, *tmp2, *src2, *x2, *ctx2, *h12, *wenc2, *wqkv2, *wo2, *w12, *w22, *wout2;
    cudaGetSymbolAddress((void**)&x,    g_x);
    cudaGetSymbolAddress((void**)&bout_pad, g_bout_pad);
    cudaGetSymbolAddress((void**)&qkv2, g_qkv2);
    cudaGetSymbolAddress((void**)&tmp2, g_tmp2);
    cudaGetSymbolAddress((void**)&src2, g_src2);
    cudaGetSymbolAddress((void**)&x2,   g_x2);
    cudaGetSymbolAddress((void**)&ctx2, g_ctx2);
    cudaGetSymbolAddress((void**)&h12,  g_h12);
    cudaGetSymbolAddress((void**)&wenc2, g_wenc2);
    cudaGetSymbolAddress((void**)&wqkv2, g_wqkv2);
    cudaGetSymbolAddress((void**)&wo2,   g_wo2);
    cudaGetSymbolAddress((void**)&w12,   g_w12);
    cudaGetSymbolAddress((void**)&w22,   g_w22);
    cudaGetSymbolAddress((void**)&wout2, g_wout2);

    // conversions
    {
        int nqA = TOK * INDIM / 4, nqB = H_ * INDIM / 4;
        int nqT = nqA + nqB;
        conv_seg2<<<(nqT + 255) / 256, 256>>>(src, Wenc, src2, wenc2, nqA, nqT);
    }
    {
        int nq = (int)((size_t)L_ * 3 * H_ * H_ / 4);
        conv_cast<<<(nq + 255) / 256, 256>>>(Wqkv, wqkv2, nq);
    }
    {
        int nq = (int)((size_t)L_ * H_ * H_ / 4);
        dim3 grid((nq + 255) / 256, 3);
        conv_cast3<<<grid, 256>>>(Wo, W1, W2, wo2, w12, w22, nq);
    }
    {
        int nq = NPADH * H_ / 4;
        conv_wout<<<(nq + 255) / 256, 256>>>(Wout, wout2, bout, bout_pad, nq);
    }
    // encoder GEMM (x fp32 + x2 fp16)
    run_gemm(src2, wenc2, benc, x, x2, TOK, H_, INDIM, H_, 1 | 2);

    for (int l = 0; l < L_; l++) {
        const __half* wqkv2_l = wqkv2 + (size_t)l * 3 * H_ * H_;
        const __half* wo2_l   = wo2   + (size_t)l * H_ * H_;
        const __half* w12_l   = w12   + (size_t)l * DFF_ * H_;
        const __half* w22_l   = w22   + (size_t)l * H_ * DFF_;
        const float* bqkv_l = bqkv + (size_t)l * 3 * H_;
        const float* bo_l   = bo   + (size_t)l * H_;
        const float* b1_l   = b1   + (size_t)l * DFF_;
        const float* b2_l   = b2   + (size_t)l * H_;

        // QKV GEMM (fp16 out)
        run_gemm(x2, wqkv2_l, bqkv_l, nullptr, qkv2, TOK, 3 * H_, H_, 3 * H_, 2);
        attn_kernel<<<(TOK * NHEAD) / 8, 256>>>(qkv2, ctx2);
        // attn_out -> fp16 tmp2
        run_gemm(ctx2, wo2_l, bo_l, nullptr, tmp2, TOK, H_, H_, H_, 2);
        resid_ln_kernel<<<TOK, 256>>>(x, tmp2, ln1_s + (size_t)l * H_, ln1_b + (size_t)l * H_, x2);
        // FF1 -> fp16 h12 (relu)
        run_gemm(x2, w12_l, b1_l, nullptr, h12, TOK, DFF_, H_, DFF_, 2 | 4);
        // FF2 -> fp16 tmp2
        run_gemm(h12, w22_l, b2_l, nullptr, tmp2, TOK, H_, DFF_, H_, 2);
        resid_ln_kernel<<<TOK, 256>>>(x, tmp2, ln2_s + (size_t)l * H_, ln2_b + (size_t)l * H_, x2);
    }

    // out = x @ Wout^T + bout  (padded N=256, masked store to 64)
    run_gemm(x2, wout2, bout_pad, out, nullptr, TOK, NPADH, H_, OUTD, 1);
}

// round 16
// speedup vs baseline: 1.5106x; 1.5106x over previous
#include <cuda_runtime.h>
#include <cuda_fp16.h>
#include <cstdint>
#include <cstddef>

#define S_    2048
#define B_    4
#define INDIM 64
#define H_    1024
#define DFF_  1024
#define OUTD  64
#define L_    3
#define NHEAD 4
#define DH    (H_ / NHEAD)   // 256
#define WIN   4
#define TOK   (S_ * B_)      // 8192
#define EPS   1e-5f
#define NPADH 256            // padded head N

// ---------------- scratch (static device globals) -----------------------------
__device__ float g_x[TOK * H_];
__device__ float g_bout_pad[NPADH];

__device__ __align__(256) __half g_qkv2[TOK * 3 * H_];
__device__ __align__(256) __half g_tmp2[TOK * H_];
__device__ __align__(256) __half g_src2[TOK * INDIM];
__device__ __align__(256) __half g_x2[TOK * H_];
__device__ __align__(256) __half g_ctx2[TOK * H_];
__device__ __align__(256) __half g_h12[TOK * H_];
__device__ __align__(256) __half g_wenc2[H_ * INDIM];
__device__ __align__(256) __half g_wqkv2[L_ * 3 * H_ * H_];
__device__ __align__(256) __half g_wo2[L_ * H_ * H_];
__device__ __align__(256) __half g_w12[L_ * DFF_ * H_];
__device__ __align__(256) __half g_w22[L_ * H_ * DFF_];
__device__ __align__(256) __half g_wout2[NPADH * H_];

// ---------------- helpers -----------------------------------------------------
__device__ __forceinline__ uint32_t smem_to_u32(const void* p) {
    uint32_t a;
    asm("{ .reg .u64 t; cvta.to.shared.u64 t, %1; cvt.u32.u64 %0, t; }"
        : "=r"(a) : "l"(p));
    return a;
}
__device__ __forceinline__ uint32_t pack_h2(__half a, __half b) {
    __half2 t = __halves2half2(a, b);
    return *reinterpret_cast<uint32_t*>(&t);
}
__device__ __forceinline__ void cp_async16(uint32_t dst, const void* src) {
    asm volatile("cp.async.cg.shared.global [%0], [%1], 16;"
                 :: "r"(dst), "l"(src) : "memory");
}
__device__ __forceinline__ void cp_commit() {
    asm volatile("cp.async.commit_group;" ::: "memory");
}
__device__ __forceinline__ void cp_wait2() {
    asm volatile("cp.async.wait_group 2;" ::: "memory");
}
__device__ __forceinline__ void ldmx4(uint32_t* r, uint32_t a) {
    asm volatile("ldmatrix.sync.aligned.m8n8.x4.shared.b16 {%0,%1,%2,%3}, [%4];"
                 : "=r"(r[0]), "=r"(r[1]), "=r"(r[2]), "=r"(r[3]) : "r"(a));
}
__device__ __forceinline__ void mma16816(float* d, const uint32_t* a,
                                         uint32_t b0, uint32_t b1) {
    asm volatile("mma.sync.aligned.m16n8k16.row.col.f32.f16.f16.f32 "
                 "{%0,%1,%2,%3}, {%4,%5,%6,%7}, {%8,%9}, {%0,%1,%2,%3};"
                 : "+f"(d[0]), "+f"(d[1]), "+f"(d[2]), "+f"(d[3])
                 : "r"(a[0]), "r"(a[1]), "r"(a[2]), "r"(a[3]), "r"(b0), "r"(b1));
}
__device__ __forceinline__ void load8h(const __half* p, float* f) {
    uint4 u = *(const uint4*)p;
    const uint32_t w[4] = { u.x, u.y, u.z, u.w };
#pragma unroll
    for (int i = 0; i < 4; i++) {
        __half2 h2 = *reinterpret_cast<const __half2*>(&w[i]);
        float2 f2 = __half22float2(h2);
        f[2 * i] = f2.x; f[2 * i + 1] = f2.y;
    }
}

// ---------------- conversion kernels ------------------------------------------
__device__ __forceinline__ void cast_quad(const float* in, uint32_t* o) {
    float4 v = *(const float4*)in;
    o[0] = pack_h2(__float2half(v.x), __float2half(v.y));
    o[1] = pack_h2(__float2half(v.z), __float2half(v.w));
}

__global__ void conv_seg2(const float* __restrict__ a, const float* __restrict__ b,
                          __half* __restrict__ oa, __half* __restrict__ ob, int nqA, int nqTot)
{
    int i = blockIdx.x * blockDim.x + threadIdx.x;
    if (i >= nqTot) return;
    if (i < nqA) cast_quad(a + 4 * (size_t)i, reinterpret_cast<uint32_t*>(oa) + 2 * (size_t)i);
    else {
        int j = i - nqA;
        cast_quad(b + 4 * (size_t)j, reinterpret_cast<uint32_t*>(ob) + 2 * (size_t)j);
    }
}

__global__ void conv_cast(const float* __restrict__ in, __half* __restrict__ out, int nq)
{
    int i = blockIdx.x * blockDim.x + threadIdx.x;
    if (i >= nq) return;
    cast_quad(in + 4 * (size_t)i, reinterpret_cast<uint32_t*>(out) + 2 * (size_t)i);
}

__global__ void conv_cast3(const float* __restrict__ a, const float* __restrict__ b,
                           const float* __restrict__ c,
                           __half* __restrict__ oa, __half* __restrict__ ob,
                           __half* __restrict__ oc, int nq)
{
    int i = blockIdx.x * blockDim.x + threadIdx.x;
    if (i >= nq) return;
    const float* in = (blockIdx.y == 0) ? a : (blockIdx.y == 1) ? b : c;
    __half* out = (blockIdx.y == 0) ? oa : (blockIdx.y == 1) ? ob : oc;
    cast_quad(in + 4 * (size_t)i, reinterpret_cast<uint32_t*>(out) + 2 * (size_t)i);
}

__global__ void conv_wout(const float* __restrict__ W, __half* __restrict__ out,
                          const float* __restrict__ bin, float* __restrict__ bpad, int nq)
{
    int i = blockIdx.x * blockDim.x + threadIdx.x;
    if (i < NPADH) bpad[i] = (i < OUTD) ? bin[i] : 0.f;
    if (i >= nq) return;
    uint32_t* o = reinterpret_cast<uint32_t*>(out) + 2 * (size_t)i;
    size_t e = 4 * (size_t)i;
    if (e < (size_t)OUTD * H_) cast_quad(W + e, o);
    else { o[0] = 0; o[1] = 0; }
}

// ---------------- fp16 HMMA GEMM (256 thr, 128x256 CTA, 64x64 warp) -----------
// C[M,Nout] = A2[M,K] @ B2[N,K]^T + bias.  M%128==0, N%256==0, K%64==0.
// mode bits: 1 = write fp32 C (cols < Nout), 2 = write fp16 C2, 4 = relu
#define NSTG  4
#define STGB  49152                 // A 16KB + B 32KB
#define GSMEM (NSTG * STGB)         // 196608

__global__ __launch_bounds__(256, 1)
void gemm_fp16(const __half* __restrict__ A2, const __half* __restrict__ B2,
               const float* __restrict__ bias, float* __restrict__ C,
               __half* __restrict__ C2,
               int M, int N, int K, int Nout, int mode)
{
    extern __shared__ char smem[];
    const uint32_t sb = smem_to_u32(smem);
    const int tid  = threadIdx.x;
    const int wid  = tid >> 5;
    const int lane = tid & 31;
    const int warp_m = wid >> 2;        // 0..1 -> 64-row block
    const int warp_n = wid & 3;         // 0..3 -> 64-col block
    const int tile_m = blockIdx.y * 128;
    const int tile_n = blockIdx.x * 256;
    const int NC = K >> 6;

    const int ra = tid >> 3;            // 0..31
    const int ca = tid & 7;
    const __half* gA = A2 + (size_t)(tile_m + ra) * K + ca * 8;
    const __half* gB = B2 + (size_t)(tile_n + ra) * K + ca * 8;
    const uint32_t dA = (uint32_t)(ra * 128 + ((ca ^ (ra & 7)) << 4));

    float acc[4][8][4];
#pragma unroll
    for (int i = 0; i < 4; i++)
#pragma unroll
        for (int j = 0; j < 8; j++)
#pragma unroll
            for (int k = 0; k < 4; k++) acc[i][j][k] = 0.f;

    auto issue = [&](int stage, int chunk) {
        uint32_t s = sb + stage * STGB;
        size_t ko = (size_t)chunk * 64;
#pragma unroll
        for (int i = 0; i < 4; i++)
            cp_async16(s + dA + i * 4096, gA + ko + (size_t)(32 * i) * K);
#pragma unroll
        for (int i = 0; i < 8; i++)
            cp_async16(s + 16384 + dA + i * 4096, gB + ko + (size_t)(32 * i) * K);
        cp_commit();
    };

    issue(0, 0);
    if (1 < NC) issue(1, 1); else cp_commit();
    if (2 < NC) issue(2, 2); else cp_commit();

    const int l16 = lane & 15;
    const int g   = lane >> 3;

    for (int c = 0; c < NC; c++) {
        cp_wait2();
        __syncthreads();
        if (c + 3 < NC) issue((c + 3) & 3, c + 3); else cp_commit();

        uint32_t sA = sb + (c & 3) * STGB;
        uint32_t sB = sA + 16384;
#pragma unroll
        for (int ks = 0; ks < 4; ks++) {
            uint32_t a[4][4];
#pragma unroll
            for (int mt = 0; mt < 4; mt++) {
                int r = warp_m * 64 + mt * 16 + l16;
                uint32_t ku = (uint32_t)((ks * 2 + (lane >> 4)) ^ (r & 7));
                ldmx4(a[mt], sA + (uint32_t)r * 128 + (ku << 4));
            }
            uint32_t b[4][4];
#pragma unroll
            for (int p = 0; p < 4; p++) {
                int rn = warp_n * 64 + p * 16 + (g >> 1) * 8 + (lane & 7);
                uint32_t ku = (uint32_t)((ks * 2 + (g & 1)) ^ (rn & 7));
                ldmx4(b[p], sB + (uint32_t)rn * 128 + (ku << 4));
            }
#pragma unroll
            for (int mt = 0; mt < 4; mt++)
#pragma unroll
                for (int p = 0; p < 4; p++) {
                    mma16816(acc[mt][2 * p],     a[mt], b[p][0], b[p][1]);
                    mma16816(acc[mt][2 * p + 1], a[mt], b[p][2], b[p][3]);
                }
        }
        // no bottom sync: next iteration's top sync orders stage reuse
    }

    // epilogue
    const int r0    = lane >> 2;
    const int cpair = (lane & 3) * 2;
#pragma unroll
    for (int mt = 0; mt < 4; mt++) {
#pragma unroll
        for (int nt = 0; nt < 8; nt++) {
            int n  = tile_n + warp_n * 64 + nt * 8 + cpair;
            int m0 = tile_m + warp_m * 64 + mt * 16 + r0;
            if (n >= Nout) continue;
            float2 bv = *(const float2*)(bias + n);
            float v[2][2];
            v[0][0] = acc[mt][nt][0] + bv.x; v[0][1] = acc[mt][nt][1] + bv.y;
            v[1][0] = acc[mt][nt][2] + bv.x; v[1][1] = acc[mt][nt][3] + bv.y;
            if (mode & 4) {
#pragma unroll
                for (int i = 0; i < 2; i++) {
                    v[i][0] = fmaxf(v[i][0], 0.f); v[i][1] = fmaxf(v[i][1], 0.f);
                }
            }
            if (mode & 1) {
                *(float2*)(C + (size_t)m0 * Nout + n)       = make_float2(v[0][0], v[0][1]);
                *(float2*)(C + (size_t)(m0 + 8) * Nout + n) = make_float2(v[1][0], v[1][1]);
            }
            if (mode & 2) {
#pragma unroll
                for (int i = 0; i < 2; i++) {
                    int m = m0 + i * 8;
                    *(reinterpret_cast<uint32_t*>(C2) + (((size_t)m * Nout + n) >> 1)) =
                        pack_h2(__float2half(v[i][0]), __float2half(v[i][1]));
                }
            }
        }
    }
}

// ---------------- banded attention (fp16 qkv in, fp16 ctx out) -----------------
__global__ __launch_bounds__(256)
void attn_kernel(const __half* __restrict__ qkv, __half* __restrict__ ctx2)
{
    int w    = (blockIdx.x * blockDim.x + threadIdx.x) >> 5;
    int lane = threadIdx.x & 31;
    if (w >= TOK * NHEAD) return;
    int t = w >> 2;
    int h = w & 3;
    int s = t / B_;
    int b = t - s * B_;

    float q[8];
    load8h(qkv + (size_t)t * (3 * H_) + h * DH + lane * 8, q);

    int lo  = s - WIN; if (lo < 0) lo = 0;
    int cnt = s - lo + 1;

    float sc[WIN + 1];
#pragma unroll
    for (int j = 0; j <= WIN; j++) {
        sc[j] = -1e30f;
        if (j < cnt) {
            int tj = (lo + j) * B_ + b;
            float k[8];
            load8h(qkv + (size_t)tj * (3 * H_) + H_ + h * DH + lane * 8, k);
            float p = 0.f;
#pragma unroll
            for (int i = 0; i < 8; i++) p = fmaf(q[i], k[i], p);
#pragma unroll
            for (int o = 16; o; o >>= 1) p += __shfl_xor_sync(0xFFFFFFFFu, p, o);
            sc[j] = p * 0.0625f;
        }
    }
    float m = sc[0];
#pragma unroll
    for (int j = 1; j <= WIN; j++) m = fmaxf(m, sc[j]);
    float e[WIN + 1];
    float se = 0.f;
#pragma unroll
    for (int j = 0; j <= WIN; j++) {
        e[j] = (j < cnt) ? __expf(sc[j] - m) : 0.f;
        se += e[j];
    }
    float inv = 1.f / se;

    float cx[8];
#pragma unroll
    for (int i = 0; i < 8; i++) cx[i] = 0.f;
    for (int j = 0; j < cnt; j++) {
        int tj = (lo + j) * B_ + b;
        float vv[8];
        load8h(qkv + (size_t)tj * (3 * H_) + 2 * H_ + h * DH + lane * 8, vv);
        float a = e[j] * inv;
#pragma unroll
        for (int i = 0; i < 8; i++) cx[i] = fmaf(a, vv[i], cx[i]);
    }

    size_t e0 = (size_t)t * H_ + h * DH + lane * 8;
    uint32_t wbuf[4];
#pragma unroll
    for (int p = 0; p < 4; p++)
        wbuf[p] = pack_h2(__float2half(cx[2 * p]), __float2half(cx[2 * p + 1]));
    *(uint4*)(reinterpret_cast<uint32_t*>(ctx2) + (e0 >> 1)) = *(uint4*)wbuf;
}

// ---------------- residual + LayerNorm (fp16 delta in, fp32+fp16 out) ---------
__device__ __forceinline__ float block_sum(float v, float* red)
{
#pragma unroll
    for (int o = 16; o; o >>= 1) v += __shfl_xor_sync(0xFFFFFFFFu, v, o);
    int wid = threadIdx.x >> 5, lane = threadIdx.x & 31;
    if (lane == 0) red[wid] = v;
    __syncthreads();
    if (threadIdx.x < 32) {
        float r = (threadIdx.x < 8) ? red[threadIdx.x] : 0.f;
#pragma unroll
        for (int o = 4; o; o >>= 1) r += __shfl_xor_sync(0xFFFFFFFFu, r, o);
        if (threadIdx.x == 0) red[0] = r;
    }
    __syncthreads();
    float r = red[0];
    __syncthreads();
    return r;
}

__global__ __launch_bounds__(256)
void resid_ln_kernel(float* __restrict__ x, const __half* __restrict__ delta2,
                     const float* __restrict__ scale, const float* __restrict__ bias,
                     __half* __restrict__ x2)
{
    __shared__ float red[8];
    int t   = blockIdx.x;
    int tid = threadIdx.x;
    size_t base = (size_t)t * H_ + tid * 4;

    float4 v = *(const float4*)(x + base);
    uint2 du = *(const uint2*)(reinterpret_cast<const uint32_t*>(delta2) + (base >> 1));
    __half2 d0 = *reinterpret_cast<const __half2*>(&du.x);
    __half2 d1 = *reinterpret_cast<const __half2*>(&du.y);
    float2 f0 = __half22float2(d0);
    float2 f1 = __half22float2(d1);
    v.x += f0.x; v.y += f0.y; v.z += f1.x; v.w += f1.y;

    float s = v.x + v.y + v.z + v.w;
    float mean = block_sum(s, red) * (1.0f / H_);

    float dx = v.x - mean, dy = v.y - mean, dz = v.z - mean, dw = v.w - mean;
    float sq = dx * dx + dy * dy + dz * dz + dw * dw;
    float var = block_sum(sq, red) * (1.0f / H_);
    float rstd = rsqrtf(var + EPS);

    float4 sc = *(const float4*)(scale + tid * 4);
    float4 bi = *(const float4*)(bias + tid * 4);
    float4 o;
    o.x = dx * rstd * sc.x + bi.x;
    o.y = dy * rstd * sc.y + bi.y;
    o.z = dz * rstd * sc.z + bi.z;
    o.w = dw * rstd * sc.w + bi.w;
    *(float4*)(x + base) = o;

    uint32_t wbuf[2];
    wbuf[0] = pack_h2(__float2half(o.x), __float2half(o.y));
    wbuf[1] = pack_h2(__float2half(o.z), __float2half(o.w));
    *(uint2*)(reinterpret_cast<uint32_t*>(x2) + (base >> 1)) = *(uint2*)wbuf;
}

// ---------------- host orchestration ------------------------------------------
static inline void run_gemm(const __half* A2, const __half* B2,
                            const float* bias, float* C, __half* C2,
                            int M, int N, int K, int Nout, int mode)
{
    static int attr_set = 0;
    if (!attr_set) {
        cudaFuncSetAttribute(gemm_fp16, cudaFuncAttributeMaxDynamicSharedMemorySize, GSMEM);
        attr_set = 1;
    }
    dim3 grid(N / 256, M / 128);
    gemm_fp16<<<grid, 256, GSMEM>>>(A2, B2, bias, C, C2, M, N, K, Nout, mode);
}

extern "C" void kernel_launch(void* const* d_in, const int* in_sizes, int n_in,
                              void* d_out, int out_size)
{
    const float* src   = (const float*)d_in[0];
    const float* Wenc  = (const float*)d_in[1];
    const float* benc  = (const float*)d_in[2];
    const float* Wqkv  = (const float*)d_in[3];
    const float* bqkv  = (const float*)d_in[4];
    const float* Wo    = (const float*)d_in[5];
    const float* bo    = (const float*)d_in[6];
    const float* W1    = (const float*)d_in[7];
    const float* b1    = (const float*)d_in[8];
    const float* W2    = (const float*)d_in[9];
    const float* b2    = (const float*)d_in[10];
    const float* ln1_s = (const float*)d_in[11];
    const float* ln1_b = (const float*)d_in[12];
    const float* ln2_s = (const float*)d_in[13];
    const float* ln2_b = (const float*)d_in[14];
    const float* Wout  = (const float*)d_in[15];
    const float* bout  = (const float*)d_in[16];
    float* out = (float*)d_out;

    float *x, *bout_pad;
    __half *qkv2, *tmp2, *src2, *x2, *ctx2, *h12, *wenc2, *wqkv2, *wo2, *w12, *w22, *wout2;
    cudaGetSymbolAddress((void**)&x,    g_x);
    cudaGetSymbolAddress((void**)&bout_pad, g_bout_pad);
    cudaGetSymbolAddress((void**)&qkv2, g_qkv2);
    cudaGetSymbolAddress((void**)&tmp2, g_tmp2);
    cudaGetSymbolAddress((void**)&src2, g_src2);
    cudaGetSymbolAddress((void**)&x2,   g_x2);
    cudaGetSymbolAddress((void**)&ctx2, g_ctx2);
    cudaGetSymbolAddress((void**)&h12,  g_h12);
    cudaGetSymbolAddress((void**)&wenc2, g_wenc2);
    cudaGetSymbolAddress((void**)&wqkv2, g_wqkv2);
    cudaGetSymbolAddress((void**)&wo2,   g_wo2);
    cudaGetSymbolAddress((void**)&w12,   g_w12);
    cudaGetSymbolAddress((void**)&w22,   g_w22);
    cudaGetSymbolAddress((void**)&wout2, g_wout2);

    // conversions
    {
        int nqA = TOK * INDIM / 4, nqB = H_ * INDIM / 4;
        int nqT = nqA + nqB;
        conv_seg2<<<(nqT + 255) / 256, 256>>>(src, Wenc, src2, wenc2, nqA, nqT);
    }
    {
        int nq = (int)((size_t)L_ * 3 * H_ * H_ / 4);
        conv_cast<<<(nq + 255) / 256, 256>>>(Wqkv, wqkv2, nq);
    }
    {
        int nq = (int)((size_t)L_ * H_ * H_ / 4);
        dim3 grid((nq + 255) / 256, 3);
        conv_cast3<<<grid, 256>>>(Wo, W1, W2, wo2, w12, w22, nq);
    }
    {
        int nq = NPADH * H_ / 4;
        conv_wout<<<(nq + 255) / 256, 256>>>(Wout, wout2, bout, bout_pad, nq);
    }
    // encoder GEMM (x fp32 + x2 fp16)
    run_gemm(src2, wenc2, benc, x, x2, TOK, H_, INDIM, H_, 1 | 2);

    for (int l = 0; l < L_; l++) {
        const __half* wqkv2_l = wqkv2 + (size_t)l * 3 * H_ * H_;
        const __half* wo2_l   = wo2   + (size_t)l * H_ * H_;
        const __half* w12_l   = w12   + (size_t)l * DFF_ * H_;
        const __half* w22_l   = w22   + (size_t)l * H_ * DFF_;
        const float* bqkv_l = bqkv + (size_t)l * 3 * H_;
        const float* bo_l   = bo   + (size_t)l * H_;
        const float* b1_l   = b1   + (size_t)l * DFF_;
        const float* b2_l   = b2   + (size_t)l * H_;

        // QKV GEMM (fp16 out)
        run_gemm(x2, wqkv2_l, bqkv_l, nullptr, qkv2, TOK, 3 * H_, H_, 3 * H_, 2);
        attn_kernel<<<(TOK * NHEAD) / 8, 256>>>(qkv2, ctx2);
        // attn_out -> fp16 tmp2
        run_gemm(ctx2, wo2_l, bo_l, nullptr, tmp2, TOK, H_, H_, H_, 2);
        resid_ln_kernel<<<TOK, 256>>>(x, tmp2, ln1_s + (size_t)l * H_, ln1_b + (size_t)l * H_, x2);
        // FF1 -> fp16 h12 (relu)
        run_gemm(x2, w12_l, b1_l, nullptr, h12, TOK, DFF_, H_, DFF_, 2 | 4);
        // FF2 -> fp16 tmp2
        run_gemm(h12, w22_l, b2_l, nullptr, tmp2, TOK, H_, DFF_, H_, 2);
        resid_ln_kernel<<<TOK, 256>>>(x, tmp2, ln2_s + (size_t)l * H_, ln2_b + (size_t)l * H_, x2);
    }

    // out = x @ Wout^T + bout  (padded N=256, masked store to 64)
    run_gemm(x2, wout2, bout_pad, out, nullptr, TOK, NPADH, H_, OUTD, 1);
}

// round 17
// speedup vs baseline: 1.5198x; 1.0061x over previous
#include <cuda_runtime.h>
#include <cuda_fp16.h>
#include <cstdint>
#include <cstddef>

#define S_    2048
#define B_    4
#define INDIM 64
#define H_    1024
#define DFF_  1024
#define OUTD  64
#define L_    3
#define NHEAD 4
#define DH    (H_ / NHEAD)   // 256
#define WIN   4
#define TOK   (S_ * B_)      // 8192
#define EPS   1e-5f
#define NPADH 256            // padded head N

// ---------------- scratch (static device globals) -----------------------------
__device__ float g_x[TOK * H_];
__device__ float g_bout_pad[NPADH];

__device__ __align__(256) __half g_qkv2[TOK * 3 * H_];
__device__ __align__(256) __half g_tmp2[TOK * H_];
__device__ __align__(256) __half g_src2[TOK * INDIM];
__device__ __align__(256) __half g_x2[TOK * H_];
__device__ __align__(256) __half g_ctx2[TOK * H_];
__device__ __align__(256) __half g_h12[TOK * H_];
__device__ __align__(256) __half g_wenc2[H_ * INDIM];
__device__ __align__(256) __half g_wqkv2[L_ * 3 * H_ * H_];
__device__ __align__(256) __half g_wo2[L_ * H_ * H_];
__device__ __align__(256) __half g_w12[L_ * DFF_ * H_];
__device__ __align__(256) __half g_w22[L_ * H_ * DFF_];
__device__ __align__(256) __half g_wout2[NPADH * H_];

// ---------------- helpers -----------------------------------------------------
__device__ __forceinline__ uint32_t smem_to_u32(const void* p) {
    uint32_t a;
    asm("{ .reg .u64 t; cvta.to.shared.u64 t, %1; cvt.u32.u64 %0, t; }"
        : "=r"(a) : "l"(p));
    return a;
}
__device__ __forceinline__ uint32_t pack_h2(__half a, __half b) {
    __half2 t = __halves2half2(a, b);
    return *reinterpret_cast<uint32_t*>(&t);
}
__device__ __forceinline__ void cp_async16(uint32_t dst, const void* src) {
    asm volatile("cp.async.cg.shared.global [%0], [%1], 16;"
                 :: "r"(dst), "l"(src) : "memory");
}
__device__ __forceinline__ void cp_commit() {
    asm volatile("cp.async.commit_group;" ::: "memory");
}
__device__ __forceinline__ void cp_wait2() {
    asm volatile("cp.async.wait_group 2;" ::: "memory");
}
__device__ __forceinline__ void ldmx4(uint32_t* r, uint32_t a) {
    asm volatile("ldmatrix.sync.aligned.m8n8.x4.shared.b16 {%0,%1,%2,%3}, [%4];"
                 : "=r"(r[0]), "=r"(r[1]), "=r"(r[2]), "=r"(r[3]) : "r"(a));
}
__device__ __forceinline__ void mma16816(float* d, const uint32_t* a,
                                         uint32_t b0, uint32_t b1) {
    asm volatile("mma.sync.aligned.m16n8k16.row.col.f32.f16.f16.f32 "
                 "{%0,%1,%2,%3}, {%4,%5,%6,%7}, {%8,%9}, {%0,%1,%2,%3};"
                 : "+f"(d[0]), "+f"(d[1]), "+f"(d[2]), "+f"(d[3])
                 : "r"(a[0]), "r"(a[1]), "r"(a[2]), "r"(a[3]), "r"(b0), "r"(b1));
}
__device__ __forceinline__ void load8h(const __half* p, float* f) {
    uint4 u = *(const uint4*)p;
    const uint32_t w[4] = { u.x, u.y, u.z, u.w };
#pragma unroll
    for (int i = 0; i < 4; i++) {
        __half2 h2 = *reinterpret_cast<const __half2*>(&w[i]);
        float2 f2 = __half22float2(h2);
        f[2 * i] = f2.x; f[2 * i + 1] = f2.y;
    }
}

// ---------------- fused conversion: all fp32->fp16 casts in one launch ---------
__device__ __forceinline__ void cast_quad(const float* in, uint32_t* o) {
    float4 v = *(const float4*)in;
    o[0] = pack_h2(__float2half(v.x), __float2half(v.y));
    o[1] = pack_h2(__float2half(v.z), __float2half(v.w));
}

// segment sizes in quads (4 fp32 elems each)
#define NQ_SRC   (TOK * INDIM / 4)                    // 131072
#define NQ_WENC  (H_ * INDIM / 4)                     // 16384
#define NQ_WQKV  ((int)((size_t)L_ * 3 * H_ * H_ / 4))// 2359296
#define NQ_WH    ((int)((size_t)L_ * H_ * H_ / 4))    // 786432
#define NQ_TOT   (NQ_SRC + NQ_WENC + NQ_WQKV + 3 * NQ_WH)

__global__ void conv_all(const float* __restrict__ src, const float* __restrict__ Wenc,
                         const float* __restrict__ Wqkv, const float* __restrict__ Wo,
                         const float* __restrict__ W1, const float* __restrict__ W2,
                         __half* __restrict__ src2, __half* __restrict__ wenc2,
                         __half* __restrict__ wqkv2, __half* __restrict__ wo2,
                         __half* __restrict__ w12, __half* __restrict__ w22)
{
    int i = blockIdx.x * blockDim.x + threadIdx.x;
    if (i >= NQ_TOT) return;
    const float* in;
    __half* out;
    int j = i;
    if (j < NQ_SRC)                 { in = src;  out = src2; }
    else if ((j -= NQ_SRC) < NQ_WENC)   { in = Wenc; out = wenc2; }
    else if ((j -= NQ_WENC) < NQ_WQKV)  { in = Wqkv; out = wqkv2; }
    else if ((j -= NQ_WQKV) < NQ_WH)    { in = Wo;   out = wo2; }
    else if ((j -= NQ_WH) < NQ_WH)      { in = W1;   out = w12; }
    else { j -= NQ_WH;                    in = W2;   out = w22; }
    cast_quad(in + 4 * (size_t)j, reinterpret_cast<uint32_t*>(out) + 2 * (size_t)j);
}

__global__ void conv_wout(const float* __restrict__ W, __half* __restrict__ out,
                          const float* __restrict__ bin, float* __restrict__ bpad, int nq)
{
    int i = blockIdx.x * blockDim.x + threadIdx.x;
    if (i < NPADH) bpad[i] = (i < OUTD) ? bin[i] : 0.f;
    if (i >= nq) return;
    uint32_t* o = reinterpret_cast<uint32_t*>(out) + 2 * (size_t)i;
    size_t e = 4 * (size_t)i;
    if (e < (size_t)OUTD * H_) cast_quad(W + e, o);
    else { o[0] = 0; o[1] = 0; }
}

// ---------------- fp16 HMMA GEMM (256 thr, 128x256 CTA, 64x64 warp) -----------
// C[M,Nout] = A2[M,K] @ B2[N,K]^T + bias.  M%128==0, N%256==0, K%64==0.
// mode bits: 1 = write fp32 C (cols < Nout), 2 = write fp16 C2, 4 = relu
#define NSTG  4
#define STGB  49152                 // A 16KB + B 32KB
#define GSMEM (NSTG * STGB)         // 196608

__global__ __launch_bounds__(256, 1)
void gemm_fp16(const __half* __restrict__ A2, const __half* __restrict__ B2,
               const float* __restrict__ bias, float* __restrict__ C,
               __half* __restrict__ C2,
               int M, int N, int K, int Nout, int mode)
{
    extern __shared__ char smem[];
    const uint32_t sb = smem_to_u32(smem);
    const int tid  = threadIdx.x;
    const int wid  = tid >> 5;
    const int lane = tid & 31;
    const int warp_m = wid >> 2;        // 0..1 -> 64-row block
    const int warp_n = wid & 3;         // 0..3 -> 64-col block
    const int tile_m = blockIdx.y * 128;
    const int tile_n = blockIdx.x * 256;
    const int NC = K >> 6;

    const int ra = tid >> 3;            // 0..31
    const int ca = tid & 7;
    const __half* gA = A2 + (size_t)(tile_m + ra) * K + ca * 8;
    const __half* gB = B2 + (size_t)(tile_n + ra) * K + ca * 8;
    const uint32_t dA = (uint32_t)(ra * 128 + ((ca ^ (ra & 7)) << 4));

    float acc[4][8][4];
#pragma unroll
    for (int i = 0; i < 4; i++)
#pragma unroll
        for (int j = 0; j < 8; j++)
#pragma unroll
            for (int k = 0; k < 4; k++) acc[i][j][k] = 0.f;

    auto issue = [&](int stage, int chunk) {
        uint32_t s = sb + stage * STGB;
        size_t ko = (size_t)chunk * 64;
#pragma unroll
        for (int i = 0; i < 4; i++)
            cp_async16(s + dA + i * 4096, gA + ko + (size_t)(32 * i) * K);
#pragma unroll
        for (int i = 0; i < 8; i++)
            cp_async16(s + 16384 + dA + i * 4096, gB + ko + (size_t)(32 * i) * K);
        cp_commit();
    };

    issue(0, 0);
    if (1 < NC) issue(1, 1); else cp_commit();
    if (2 < NC) issue(2, 2); else cp_commit();

    const int l16 = lane & 15;
    const int g   = lane >> 3;

    for (int c = 0; c < NC; c++) {
        cp_wait2();
        __syncthreads();
        if (c + 3 < NC) issue((c + 3) & 3, c + 3); else cp_commit();

        uint32_t sA = sb + (c & 3) * STGB;
        uint32_t sB = sA + 16384;
#pragma unroll
        for (int ks = 0; ks < 4; ks++) {
            uint32_t a[4][4];
#pragma unroll
            for (int mt = 0; mt < 4; mt++) {
                int r = warp_m * 64 + mt * 16 + l16;
                uint32_t ku = (uint32_t)((ks * 2 + (lane >> 4)) ^ (r & 7));
                ldmx4(a[mt], sA + (uint32_t)r * 128 + (ku << 4));
            }
            uint32_t b[4][4];
#pragma unroll
            for (int p = 0; p < 4; p++) {
                int rn = warp_n * 64 + p * 16 + (g >> 1) * 8 + (lane & 7);
                uint32_t ku = (uint32_t)((ks * 2 + (g & 1)) ^ (rn & 7));
                ldmx4(b[p], sB + (uint32_t)rn * 128 + (ku << 4));
            }
#pragma unroll
            for (int mt = 0; mt < 4; mt++)
#pragma unroll
                for (int p = 0; p < 4; p++) {
                    mma16816(acc[mt][2 * p],     a[mt], b[p][0], b[p][1]);
                    mma16816(acc[mt][2 * p + 1], a[mt], b[p][2], b[p][3]);
                }
        }
        // no bottom sync: next iteration's top sync orders stage reuse
    }

    // epilogue
    const int r0    = lane >> 2;
    const int cpair = (lane & 3) * 2;
#pragma unroll
    for (int mt = 0; mt < 4; mt++) {
#pragma unroll
        for (int nt = 0; nt < 8; nt++) {
            int n  = tile_n + warp_n * 64 + nt * 8 + cpair;
            int m0 = tile_m + warp_m * 64 + mt * 16 + r0;
            if (n >= Nout) continue;
            float2 bv = *(const float2*)(bias + n);
            float v[2][2];
            v[0][0] = acc[mt][nt][0] + bv.x; v[0][1] = acc[mt][nt][1] + bv.y;
            v[1][0] = acc[mt][nt][2] + bv.x; v[1][1] = acc[mt][nt][3] + bv.y;
            if (mode & 4) {
#pragma unroll
                for (int i = 0; i < 2; i++) {
                    v[i][0] = fmaxf(v[i][0], 0.f); v[i][1] = fmaxf(v[i][1], 0.f);
                }
            }
            if (mode & 1) {
                *(float2*)(C + (size_t)m0 * Nout + n)       = make_float2(v[0][0], v[0][1]);
                *(float2*)(C + (size_t)(m0 + 8) * Nout + n) = make_float2(v[1][0], v[1][1]);
            }
            if (mode & 2) {
#pragma unroll
                for (int i = 0; i < 2; i++) {
                    int m = m0 + i * 8;
                    *(reinterpret_cast<uint32_t*>(C2) + (((size_t)m * Nout + n) >> 1)) =
                        pack_h2(__float2half(v[i][0]), __float2half(v[i][1]));
                }
            }
        }
    }
}

// ---------------- banded attention (fp16 qkv in, fp16 ctx out) -----------------
__global__ __launch_bounds__(256)
void attn_kernel(const __half* __restrict__ qkv, __half* __restrict__ ctx2)
{
    int w    = (blockIdx.x * blockDim.x + threadIdx.x) >> 5;
    int lane = threadIdx.x & 31;
    if (w >= TOK * NHEAD) return;
    int t = w >> 2;
    int h = w & 3;
    int s = t / B_;
    int b = t - s * B_;

    float q[8];
    load8h(qkv + (size_t)t * (3 * H_) + h * DH + lane * 8, q);

    int lo  = s - WIN; if (lo < 0) lo = 0;
    int cnt = s - lo + 1;

    float sc[WIN + 1];
#pragma unroll
    for (int j = 0; j <= WIN; j++) {
        sc[j] = -1e30f;
        if (j < cnt) {
            int tj = (lo + j) * B_ + b;
            float k[8];
            load8h(qkv + (size_t)tj * (3 * H_) + H_ + h * DH + lane * 8, k);
            float p = 0.f;
#pragma unroll
            for (int i = 0; i < 8; i++) p = fmaf(q[i], k[i], p);
#pragma unroll
            for (int o = 16; o; o >>= 1) p += __shfl_xor_sync(0xFFFFFFFFu, p, o);
            sc[j] = p * 0.0625f;
        }
    }
    float m = sc[0];
#pragma unroll
    for (int j = 1; j <= WIN; j++) m = fmaxf(m, sc[j]);
    float e[WIN + 1];
    float se = 0.f;
#pragma unroll
    for (int j = 0; j <= WIN; j++) {
        e[j] = (j < cnt) ? __expf(sc[j] - m) : 0.f;
        se += e[j];
    }
    float inv = 1.f / se;

    float cx[8];
#pragma unroll
    for (int i = 0; i < 8; i++) cx[i] = 0.f;
    for (int j = 0; j < cnt; j++) {
        int tj = (lo + j) * B_ + b;
        float vv[8];
        load8h(qkv + (size_t)tj * (3 * H_) + 2 * H_ + h * DH + lane * 8, vv);
        float a = e[j] * inv;
#pragma unroll
        for (int i = 0; i < 8; i++) cx[i] = fmaf(a, vv[i], cx[i]);
    }

    size_t e0 = (size_t)t * H_ + h * DH + lane * 8;
    uint32_t wbuf[4];
#pragma unroll
    for (int p = 0; p < 4; p++)
        wbuf[p] = pack_h2(__float2half(cx[2 * p]), __float2half(cx[2 * p + 1]));
    *(uint4*)(reinterpret_cast<uint32_t*>(ctx2) + (e0 >> 1)) = *(uint4*)wbuf;
}

// ---------------- residual + LayerNorm (fp16 delta in, fp32+fp16 out) ---------
__device__ __forceinline__ float block_sum(float v, float* red)
{
#pragma unroll
    for (int o = 16; o; o >>= 1) v += __shfl_xor_sync(0xFFFFFFFFu, v, o);
    int wid = threadIdx.x >> 5, lane = threadIdx.x & 31;
    if (lane == 0) red[wid] = v;
    __syncthreads();
    if (threadIdx.x < 32) {
        float r = (threadIdx.x < 8) ? red[threadIdx.x] : 0.f;
#pragma unroll
        for (int o = 4; o; o >>= 1) r += __shfl_xor_sync(0xFFFFFFFFu, r, o);
        if (threadIdx.x == 0) red[0] = r;
    }
    __syncthreads();
    float r = red[0];
    __syncthreads();
    return r;
}

__global__ __launch_bounds__(256)
void resid_ln_kernel(float* __restrict__ x, const __half* __restrict__ delta2,
                     const float* __restrict__ scale, const float* __restrict__ bias,
                     __half* __restrict__ x2)
{
    __shared__ float red[8];
    int t   = blockIdx.x;
    int tid = threadIdx.x;
    size_t base = (size_t)t * H_ + tid * 4;

    float4 v = *(const float4*)(x + base);
    uint2 du = *(const uint2*)(reinterpret_cast<const uint32_t*>(delta2) + (base >> 1));
    __half2 d0 = *reinterpret_cast<const __half2*>(&du.x);
    __half2 d1 = *reinterpret_cast<const __half2*>(&du.y);
    float2 f0 = __half22float2(d0);
    float2 f1 = __half22float2(d1);
    v.x += f0.x; v.y += f0.y; v.z += f1.x; v.w += f1.y;

    float s = v.x + v.y + v.z + v.w;
    float mean = block_sum(s, red) * (1.0f / H_);

    float dx = v.x - mean, dy = v.y - mean, dz = v.z - mean, dw = v.w - mean;
    float sq = dx * dx + dy * dy + dz * dz + dw * dw;
    float var = block_sum(sq, red) * (1.0f / H_);
    float rstd = rsqrtf(var + EPS);

    float4 sc = *(const float4*)(scale + tid * 4);
    float4 bi = *(const float4*)(bias + tid * 4);
    float4 o;
    o.x = dx * rstd * sc.x + bi.x;
    o.y = dy * rstd * sc.y + bi.y;
    o.z = dz * rstd * sc.z + bi.z;
    o.w = dw * rstd * sc.w + bi.w;
    *(float4*)(x + base) = o;

    uint32_t wbuf[2];
    wbuf[0] = pack_h2(__float2half(o.x), __float2half(o.y));
    wbuf[1] = pack_h2(__float2half(o.z), __float2half(o.w));
    *(uint2*)(reinterpret_cast<uint32_t*>(x2) + (base >> 1)) = *(uint2*)wbuf;
}

// ---------------- host orchestration ------------------------------------------
static inline void run_gemm(const __half* A2, const __half* B2,
                            const float* bias, float* C, __half* C2,
                            int M, int N, int K, int Nout, int mode)
{
    static int attr_set = 0;
    if (!attr_set) {
        cudaFuncSetAttribute(gemm_fp16, cudaFuncAttributeMaxDynamicSharedMemorySize, GSMEM);
        attr_set = 1;
    }
    dim3 grid(N / 256, M / 128);
    gemm_fp16<<<grid, 256, GSMEM>>>(A2, B2, bias, C, C2, M, N, K, Nout, mode);
}

extern "C" void kernel_launch(void* const* d_in, const int* in_sizes, int n_in,
                              void* d_out, int out_size)
{
    const float* src   = (const float*)d_in[0];
    const float* Wenc  = (const float*)d_in[1];
    const float* benc  = (const float*)d_in[2];
    const float* Wqkv  = (const float*)d_in[3];
    const float* bqkv  = (const float*)d_in[4];
    const float* Wo    = (const float*)d_in[5];
    const float* bo    = (const float*)d_in[6];
    const float* W1    = (const float*)d_in[7];
    const float* b1    = (const float*)d_in[8];
    const float* W2    = (const float*)d_in[9];
    const float* b2    = (const float*)d_in[10];
    const float* ln1_s = (const float*)d_in[11];
    const float* ln1_b = (const float*)d_in[12];
    const float* ln2_s = (const float*)d_in[13];
    const float* ln2_b = (const float*)d_in[14];
    const float* Wout  = (const float*)d_in[15];
    const float* bout  = (const float*)d_in[16];
    float* out = (float*)d_out;

    float *x, *bout_pad;
    __half *qkv2, *tmp2, *src2, *x2, *ctx2, *h12, *wenc2, *wqkv2, *wo2, *w12, *w22, *wout2;
    cudaGetSymbolAddress((void**)&x,    g_x);
    cudaGetSymbolAddress((void**)&bout_pad, g_bout_pad);
    cudaGetSymbolAddress((void**)&qkv2, g_qkv2);
    cudaGetSymbolAddress((void**)&tmp2, g_tmp2);
    cudaGetSymbolAddress((void**)&src2, g_src2);
    cudaGetSymbolAddress((void**)&x2,   g_x2);
    cudaGetSymbolAddress((void**)&ctx2, g_ctx2);
    cudaGetSymbolAddress((void**)&h12,  g_h12);
    cudaGetSymbolAddress((void**)&wenc2, g_wenc2);
    cudaGetSymbolAddress((void**)&wqkv2, g_wqkv2);
    cudaGetSymbolAddress((void**)&wo2,   g_wo2);
    cudaGetSymbolAddress((void**)&w12,   g_w12);
    cudaGetSymbolAddress((void**)&w22,   g_w22);
    cudaGetSymbolAddress((void**)&wout2, g_wout2);

    // launch 0: all main conversions fused
    conv_all<<<(NQ_TOT + 255) / 256, 256>>>(src, Wenc, Wqkv, Wo, W1, W2,
                                            src2, wenc2, wqkv2, wo2, w12, w22);
    // launch 1: Wout pad-cast + bias pad
    {
        int nq = NPADH * H_ / 4;
        conv_wout<<<(nq + 255) / 256, 256>>>(Wout, wout2, bout, bout_pad, nq);
    }
    // launch 2: encoder GEMM (x fp32 + x2 fp16)
    run_gemm(src2, wenc2, benc, x, x2, TOK, H_, INDIM, H_, 1 | 2);

    for (int l = 0; l < L_; l++) {
        const __half* wqkv2_l = wqkv2 + (size_t)l * 3 * H_ * H_;
        const __half* wo2_l   = wo2   + (size_t)l * H_ * H_;
        const __half* w12_l   = w12   + (size_t)l * DFF_ * H_;
        const __half* w22_l   = w22   + (size_t)l * H_ * DFF_;
        const float* bqkv_l = bqkv + (size_t)l * 3 * H_;
        const float* bo_l   = bo   + (size_t)l * H_;
        const float* b1_l   = b1   + (size_t)l * DFF_;
        const float* b2_l   = b2   + (size_t)l * H_;

        // launch 3 (layer 0): QKV GEMM -> profiled slot (-s 5 == our idx 3)
        run_gemm(x2, wqkv2_l, bqkv_l, nullptr, qkv2, TOK, 3 * H_, H_, 3 * H_, 2);
        attn_kernel<<<(TOK * NHEAD) / 8, 256>>>(qkv2, ctx2);
        run_gemm(ctx2, wo2_l, bo_l, nullptr, tmp2, TOK, H_, H_, H_, 2);
        resid_ln_kernel<<<TOK, 256>>>(x, tmp2, ln1_s + (size_t)l * H_, ln1_b + (size_t)l * H_, x2);
        run_gemm(x2, w12_l, b1_l, nullptr, h12, TOK, DFF_, H_, DFF_, 2 | 4);
        run_gemm(h12, w22_l, b2_l, nullptr, tmp2, TOK, H_, DFF_, H_, 2);
        resid_ln_kernel<<<TOK, 256>>>(x, tmp2, ln2_s + (size_t)l * H_, ln2_b + (size_t)l * H_, x2);
    }

    // out = x @ Wout^T + bout  (padded N=256, masked store to 64)
    run_gemm(x2, wout2, bout_pad, out, nullptr, TOK, NPADH, H_, OUTD, 1);
}